// round 11
// baseline (speedup 1.0000x reference)
#include <cuda_runtime.h>

#define IMG 28
#define NU 96
#define SDIM (IMG * NU)            // 2688
#define NUNITS (NU * NU)           // 9216
#define ROWV4 (SDIM / 4)           // 672 float4s per row
#define NV4 ((SDIM * SDIM) / 4)    // 1806336 float4s per plane

#define K1_ROWS_PER_CTA 3
#define K1_GRID (SDIM / K1_ROWS_PER_CTA)         // 896 CTAs
#define K1_F4_PER_CTA (K1_ROWS_PER_CTA * ROWV4)  // 2016
#define K1_NACC (K1_ROWS_PER_CTA * NU)           // 288 accumulators

__device__ float g_unit_map[NUNITS];             // static-zeroed; k2 re-zeroes
__device__ float g_fm[NUNITS];
__device__ float g_va[NUNITS];

// ---------------------------------------------------------------------------
// Kernel 1: unit_map[i][j] = sum over 28x28 block of (som - x)^2 / rv.
// FLAT layout: each CTA streams 3 full rows (2016 float4s x2 arrays) with
// PERFECTLY contiguous warp loads (512B per warp-LDG.128). A float4 never
// straddles a unit boundary (28 % 4 == 0), so the per-unit reduction is a
// segmented smem atomicAdd (96 accumulators per row, conflict degree <= 7),
// followed by 288 global atomicAdds per CTA into g_unit_map.
// Replaces warp-per-unit, whose scattered 112B segments cost ~2.5x in
// L1tex wavefronts and pinned DRAM at ~45% for four rounds straight.
// ---------------------------------------------------------------------------
__global__ __launch_bounds__(256) void k_block_sums(
        const float* __restrict__ som,
        const float* __restrict__ rv,
        const float* __restrict__ x) {
    __shared__ float sm_acc[K1_NACC];            // 288 accumulators
    __shared__ float sm_x[IMG * IMG];            // 784 floats, 3.1 KB

    const int t = threadIdx.x;

    // stage x (once per CTA) + zero accumulators (288 = 256 + 32)
    if (t < 196) ((float4*)sm_x)[t] = ((const float4*)x)[t];
    sm_acc[t] = 0.0f;
    if (t < K1_NACC - 256) sm_acc[256 + t] = 0.0f;
    __syncthreads();

    const unsigned cta_f4 = blockIdx.x * K1_F4_PER_CTA;
    const int row0 = blockIdx.x * K1_ROWS_PER_CTA;

#pragma unroll
    for (int p = t; p < K1_F4_PER_CTA; p += 256) {
        const unsigned g4 = cta_f4 + p;          // global float4 index
        const int lr  = p / ROWV4;               // local row 0..2
        const int pos = p - lr * ROWV4;          // float4 within row 0..671
        const int j   = pos / 7;                 // unit column
        const int q   = pos - j * 7;             // float4 within unit segment
        const int a   = (row0 + lr) % IMG;       // row within 28x28 block

        const float4 s4 = ((const float4*)som)[g4];
        const float4 r4 = ((const float4*)rv)[g4];
        const float4 x4 = ((const float4*)sm_x)[a * 7 + q];

        float d0 = s4.x - x4.x;
        float d1 = s4.y - x4.y;
        float d2 = s4.z - x4.z;
        float d3 = s4.w - x4.w;
        float v = __fdividef(d0 * d0, r4.x) + __fdividef(d1 * d1, r4.y)
                + __fdividef(d2 * d2, r4.z) + __fdividef(d3 * d3, r4.w);

        atomicAdd_block(&sm_acc[lr * NU + j], v);
    }
    __syncthreads();

    // publish: 288 per-row-unit partials -> global unit accumulators
    {
        const int lr = t / NU;
        const int jj = t - lr * NU;
        const int i  = (row0 + lr) / IMG;        // unit row
        atomicAdd(&g_unit_map[i * NU + jj], sm_acc[t]);
    }
    if (t < K1_NACC - 256) {
        const int tt = 256 + t;
        const int lr = tt / NU;
        const int jj = tt - lr * NU;
        const int i  = (row0 + lr) / IMG;
        atomicAdd(&g_unit_map[i * NU + jj], sm_acc[tt]);
    }
}

// ---------------------------------------------------------------------------
// Kernel 2: single CTA. Argmin over unit_map (first-occurrence tiebreak),
// then the 96x96 final_modifier / variance_alpha maps, then RE-ZEROES
// g_unit_map so the next graph replay accumulates from zero.
// cartesian_distances[i,j,bi,bj] == sqrt((i-bi)^2 + (j-bj)^2) -> analytic.
// ---------------------------------------------------------------------------
__global__ void k_modifiers(const float* __restrict__ lr_map,
                            const float* __restrict__ radius) {
    const int t = threadIdx.x;  // 1024 threads
    __shared__ float vmin[1024];
    __shared__ int   imin[1024];

    float bv = 3.4028235e38f;
    int   bidx = 0;
    for (int u = t; u < NUNITS; u += 1024) {
        float v = g_unit_map[u];
        if (v < bv) { bv = v; bidx = u; }
    }
    vmin[t] = bv;
    imin[t] = bidx;
    __syncthreads();
#pragma unroll
    for (int s = 512; s > 0; s >>= 1) {
        if (t < s) {
            float ov = vmin[t + s];
            int   oi = imin[t + s];
            if (ov < vmin[t] || (ov == vmin[t] && oi < imin[t])) {
                vmin[t] = ov;
                imin[t] = oi;
            }
        }
        __syncthreads();
    }

    const int best = imin[0];
    const int bi = best / NU;
    const int bj = best % NU;
    const float r   = radius[best];
    const float lrb = lr_map[best];
    const float dist_mod = 1.0f / (2.0f * r * r);
    const float constant = -logf(1e-8f / lrb) / dist_mod;

    for (int u = t; u < NUNITS; u += 1024) {
        const int ii = u / NU;
        const int jj = u % NU;
        const float di = (float)(ii - bi);
        const float dj = (float)(jj - bj);
        const float d = sqrtf(di * di + dj * dj);
        float mask = (d > r) ? 0.0f : 1.0f;
        float fm = mask * lr_map[u] * expf(-d * dist_mod);
        float alpha = (0.9f - 0.5f) + 1.0f / (1.0f + expf(-d / constant));
        alpha = alpha * mask + (1.0f - mask);
        alpha = fminf(fmaxf(alpha, 0.0f), 1.0f);
        g_fm[u] = fm;
        g_va[u] = alpha;
        g_unit_map[u] = 0.0f;                 // reset for next replay
    }
}

// ---------------------------------------------------------------------------
// Kernel 3: elementwise update. K3_BATCH=2 (~32 regs) -> 8 CTAs/SM.
// Streaming stores (__stcs) keep the never-re-read output from evicting
// som/rv in L2. out[0] = som_new, out[1] = var_new.
// ---------------------------------------------------------------------------
#define K3_BATCH 2
__global__ __launch_bounds__(256) void k_update(
        const float* __restrict__ som,
        const float* __restrict__ rv,
        const float* __restrict__ x,
        float* __restrict__ out) {
    const unsigned base = blockIdx.x * (256 * K3_BATCH) + threadIdx.x;

    unsigned idx[K3_BATCH];
    float4 s4[K3_BATCH], r4[K3_BATCH], x4[K3_BATCH];
    float fm[K3_BATCH], va[K3_BATCH];

#pragma unroll
    for (int k = 0; k < K3_BATCH; k++) {
        idx[k] = base + k * 256;
        s4[k] = *(const float4*)(som + (size_t)idx[k] * 4);
        r4[k] = *(const float4*)(rv + (size_t)idx[k] * 4);
    }
#pragma unroll
    for (int k = 0; k < K3_BATCH; k++) {
        const int row = idx[k] / ROWV4;
        const int c4  = idx[k] % ROWV4;
        const int col = c4 * 4;
        const int i = row / IMG;
        const int a = row % IMG;
        const int j = col / IMG;
        const int b = col % IMG;           // multiple of 4 (28 % 4 == 0)
        fm[k] = g_fm[i * NU + j];
        va[k] = g_va[i * NU + j];
        x4[k] = *(const float4*)(x + a * IMG + b);
    }

#pragma unroll
    for (int k = 0; k < K3_BATCH; k++) {
        float4 sn, vn;
#define DO_LANE(L)                                                   \
        {                                                            \
            float s_ = s4[k].L;                                      \
            float xv = x4[k].L;                                      \
            float snew = s_ + fm[k] * (xv - s_);                     \
            snew = fminf(fmaxf(snew, 0.0f), 1.0f);                   \
            float dd = xv - snew;                                    \
            sn.L = snew;                                             \
            vn.L = va[k] * r4[k].L + (1.0f - va[k]) * dd * dd;       \
        }
        DO_LANE(x) DO_LANE(y) DO_LANE(z) DO_LANE(w)
#undef DO_LANE
        __stcs((float4*)out + idx[k], sn);
        __stcs((float4*)out + idx[k] + NV4, vn);
    }
}

// ---------------------------------------------------------------------------
// Launch
// inputs: 0=som, 1=running_variance, 2=learning_rates, 3=radius,
//         4=cartesian_distances (unused; analytic), 5=x
// out = (2, 2688, 2688) float32
// ---------------------------------------------------------------------------
extern "C" void kernel_launch(void* const* d_in, const int* in_sizes, int n_in,
                              void* d_out, int out_size) {
    const float* som  = (const float*)d_in[0];
    const float* rv   = (const float*)d_in[1];
    const float* lr   = (const float*)d_in[2];
    const float* rad  = (const float*)d_in[3];
    const float* x    = (const float*)d_in[5];
    float* out = (float*)d_out;

    k_block_sums<<<K1_GRID, 256>>>(som, rv, x);
    k_modifiers<<<1, 1024>>>(lr, rad);
    k_update<<<NV4 / (256 * K3_BATCH), 256>>>(som, rv, x, out);
}

// round 12
// speedup vs baseline: 1.0504x; 1.0504x over previous
#include <cuda_runtime.h>

#define IMG 28
#define NU 96
#define SDIM (IMG * NU)            // 2688
#define NUNITS (NU * NU)           // 9216
#define ROWV4 (SDIM / 4)           // 672 float4s per row
#define NV4 ((SDIM * SDIM) / 4)    // 1806336 float4s per plane
#define SEGS (SDIM * NU)           // 258048 unit-segments (7 f4s each)
#define K1_GRID 888                // 6 x 148: exactly one wave, no tail

__device__ float g_unit_map[NUNITS];   // static-zeroed; k2 re-zeroes each replay
__device__ float g_fm[NUNITS];
__device__ float g_va[NUNITS];

// ---------------------------------------------------------------------------
// Kernel 1: unit_map[i][j] = sum over 28x28 block of (som - x)^2 / rv.
// Flat streaming (perfectly coalesced 512B warp loads) + WARP-SEGMENTED
// shuffle reduction. A unit-segment = 7 consecutive float4s (28 floats,
// 28%4==0 so f4s never straddle units; 672 % 7 == 0 so p%7 is the in-segment
// phase). Suffix-sum with deltas 1,2,4 (covers length<=8>=7) collapses each
// segment in registers; only segment-start lanes (<=6/warp, distinct
// addresses) do a global no-return atomicAdd. This removes R11's conflicted
// smem ATOMS (L1TEX was 43% busy) and all block-level reduction overhead.
// Grid = 888 CTAs, segment-aligned balanced partition (+-1 segment) -> one
// full wave at 6 CTAs/SM, no quantization tail.
// ---------------------------------------------------------------------------
__global__ __launch_bounds__(256) void k_block_sums(
        const float* __restrict__ som,
        const float* __restrict__ rv,
        const float* __restrict__ x) {
    __shared__ float sm_x[IMG * IMG];            // 784 floats, 3.1 KB

    const int t = threadIdx.x;
    if (t < 196) ((float4*)sm_x)[t] = ((const float4*)x)[t];
    __syncthreads();

    // segment-aligned CTA partition: CTA c handles segments [s0, s1)
    const unsigned s0 = (unsigned)(((unsigned long long)blockIdx.x * SEGS) / K1_GRID);
    const unsigned s1 = (unsigned)(((unsigned long long)(blockIdx.x + 1) * SEGS) / K1_GRID);
    const unsigned p_end = s1 * 7;               // f4 range end (exclusive)
    const int lane = t & 31;

    // warp-uniform loop: wb is the warp's base f4 index
    for (unsigned wb = s0 * 7 + (unsigned)(t - lane); wb < p_end; wb += 256) {
        const unsigned p = wb + lane;            // this lane's global f4 index
        const bool active = (p < p_end);
        const unsigned r = p % 7;                // phase within unit-segment

        float v = 0.0f;
        if (active) {
            const unsigned row = p / ROWV4;      // global row 0..2687
            const unsigned a = row % IMG;        // row within 28x28 block
            const float4 s4 = ((const float4*)som)[p];
            const float4 r4 = ((const float4*)rv)[p];
            const float4 x4 = ((const float4*)sm_x)[a * 7 + r];
            float d0 = s4.x - x4.x;
            float d1 = s4.y - x4.y;
            float d2 = s4.z - x4.z;
            float d3 = s4.w - x4.w;
            v = __fdividef(d0 * d0, r4.x) + __fdividef(d1 * d1, r4.y)
              + __fdividef(d2 * d2, r4.z) + __fdividef(d3 * d3, r4.w);
        }

        // segmented suffix-sum: after deltas 1,2,4 the first lane of each
        // segment(-part) holds the sum of its in-warp segment lanes
#pragma unroll
        for (int d = 1; d <= 4; d <<= 1) {
            float o = __shfl_down_sync(0xFFFFFFFFu, v, d);
            if ((r + d < 7) && (lane + d < 32)) v += o;
        }

        // segment-start lanes publish (lane 0 also covers warp-split tails)
        if (active && (r == 0 || lane == 0)) {
            const unsigned seg = p / 7;          // = row*96 + j
            const unsigned row = seg / NU;
            const unsigned j = seg - row * NU;
            const unsigned i = row / IMG;
            atomicAdd(&g_unit_map[i * NU + j], v);
        }
    }
}

// ---------------------------------------------------------------------------
// Kernel 2: single CTA. Argmin over unit_map (first-occurrence tiebreak),
// then the 96x96 final_modifier / variance_alpha maps, then RE-ZEROES
// g_unit_map so the next graph replay accumulates from zero.
// cartesian_distances[i,j,bi,bj] == sqrt((i-bi)^2 + (j-bj)^2) -> analytic.
// ---------------------------------------------------------------------------
__global__ void k_modifiers(const float* __restrict__ lr_map,
                            const float* __restrict__ radius) {
    const int t = threadIdx.x;  // 1024 threads
    __shared__ float vmin[1024];
    __shared__ int   imin[1024];

    float bv = 3.4028235e38f;
    int   bidx = 0;
    for (int u = t; u < NUNITS; u += 1024) {
        float v = g_unit_map[u];
        if (v < bv) { bv = v; bidx = u; }
    }
    vmin[t] = bv;
    imin[t] = bidx;
    __syncthreads();
#pragma unroll
    for (int s = 512; s > 0; s >>= 1) {
        if (t < s) {
            float ov = vmin[t + s];
            int   oi = imin[t + s];
            if (ov < vmin[t] || (ov == vmin[t] && oi < imin[t])) {
                vmin[t] = ov;
                imin[t] = oi;
            }
        }
        __syncthreads();
    }

    const int best = imin[0];
    const int bi = best / NU;
    const int bj = best % NU;
    const float r   = radius[best];
    const float lrb = lr_map[best];
    const float dist_mod = 1.0f / (2.0f * r * r);
    const float constant = -logf(1e-8f / lrb) / dist_mod;

    for (int u = t; u < NUNITS; u += 1024) {
        const int ii = u / NU;
        const int jj = u % NU;
        const float di = (float)(ii - bi);
        const float dj = (float)(jj - bj);
        const float d = sqrtf(di * di + dj * dj);
        float mask = (d > r) ? 0.0f : 1.0f;
        float fm = mask * lr_map[u] * expf(-d * dist_mod);
        float alpha = (0.9f - 0.5f) + 1.0f / (1.0f + expf(-d / constant));
        alpha = alpha * mask + (1.0f - mask);
        alpha = fminf(fmaxf(alpha, 0.0f), 1.0f);
        g_fm[u] = fm;
        g_va[u] = alpha;
        g_unit_map[u] = 0.0f;                 // reset for next replay
    }
}

// ---------------------------------------------------------------------------
// Kernel 3: elementwise update. K3_BATCH=2 (~32 regs) -> 8 CTAs/SM.
// Streaming stores (__stcs) keep the never-re-read output from evicting
// som/rv in L2. out[0] = som_new, out[1] = var_new.
// ---------------------------------------------------------------------------
#define K3_BATCH 2
__global__ __launch_bounds__(256) void k_update(
        const float* __restrict__ som,
        const float* __restrict__ rv,
        const float* __restrict__ x,
        float* __restrict__ out) {
    const unsigned base = blockIdx.x * (256 * K3_BATCH) + threadIdx.x;

    unsigned idx[K3_BATCH];
    float4 s4[K3_BATCH], r4[K3_BATCH], x4[K3_BATCH];
    float fm[K3_BATCH], va[K3_BATCH];

#pragma unroll
    for (int k = 0; k < K3_BATCH; k++) {
        idx[k] = base + k * 256;
        s4[k] = *(const float4*)(som + (size_t)idx[k] * 4);
        r4[k] = *(const float4*)(rv + (size_t)idx[k] * 4);
    }
#pragma unroll
    for (int k = 0; k < K3_BATCH; k++) {
        const int row = idx[k] / ROWV4;
        const int c4  = idx[k] % ROWV4;
        const int col = c4 * 4;
        const int i = row / IMG;
        const int a = row % IMG;
        const int j = col / IMG;
        const int b = col % IMG;           // multiple of 4 (28 % 4 == 0)
        fm[k] = g_fm[i * NU + j];
        va[k] = g_va[i * NU + j];
        x4[k] = *(const float4*)(x + a * IMG + b);
    }

#pragma unroll
    for (int k = 0; k < K3_BATCH; k++) {
        float4 sn, vn;
#define DO_LANE(L)                                                   \
        {                                                            \
            float s_ = s4[k].L;                                      \
            float xv = x4[k].L;                                      \
            float snew = s_ + fm[k] * (xv - s_);                     \
            snew = fminf(fmaxf(snew, 0.0f), 1.0f);                   \
            float dd = xv - snew;                                    \
            sn.L = snew;                                             \
            vn.L = va[k] * r4[k].L + (1.0f - va[k]) * dd * dd;       \
        }
        DO_LANE(x) DO_LANE(y) DO_LANE(z) DO_LANE(w)
#undef DO_LANE
        __stcs((float4*)out + idx[k], sn);
        __stcs((float4*)out + idx[k] + NV4, vn);
    }
}

// ---------------------------------------------------------------------------
// Launch
// inputs: 0=som, 1=running_variance, 2=learning_rates, 3=radius,
//         4=cartesian_distances (unused; analytic), 5=x
// out = (2, 2688, 2688) float32
// ---------------------------------------------------------------------------
extern "C" void kernel_launch(void* const* d_in, const int* in_sizes, int n_in,
                              void* d_out, int out_size) {
    const float* som  = (const float*)d_in[0];
    const float* rv   = (const float*)d_in[1];
    const float* lr   = (const float*)d_in[2];
    const float* rad  = (const float*)d_in[3];
    const float* x    = (const float*)d_in[5];
    float* out = (float*)d_out;

    k_block_sums<<<K1_GRID, 256>>>(som, rv, x);
    k_modifiers<<<1, 1024>>>(lr, rad);
    k_update<<<NV4 / (256 * K3_BATCH), 256>>>(som, rv, x, out);
}